// round 13
// baseline (speedup 1.0000x reference)
#include <cuda_runtime.h>
#include <cuda_fp16.h>
#include <cstdint>
#include <math.h>

// ---------------- problem constants ----------------
#define G        160
#define V        (G*G*G)          // 4,096,000 voxels
#define NRAYS    4096
#define S        256
#define NS       (NRAYS*S)        // 1,048,576 samples
#define ACT_SHIFT (-4.5951198501345898f)   // log(0.01/0.99)

#define FSTR     24               // fp16 elems/row, feat + w0 tiles (K=16 incl pad)
#define HSTR     136              // fp16 elems/row, w1 tiles (K=128 + pad)
#define GRID_MLP 304

// ---------------- scratch ----------------
// packed voxel: bytes 0-23 = ch0..11 fp16, bytes 24-27 = density fp32, 28-31 pad
__device__ uint4 g_pack[(size_t)V * 2];
__device__ float g_b0r[(size_t)NRAYS * 128];// per-ray fused bias: b0 + emb@w0[12:39]

// ---------------- smem layout (byte offsets) ----------------
#define FEAT_OFF  0                            // 256 x FSTR fp16 = 12288
#define W0_OFF    (FEAT_OFF + 256*FSTR*2)      // 12288 (+6144)
#define W1_OFF    (W0_OFF   + 128*FSTR*2)      // 18432 (+34816)
#define SPQ_OFF   (W1_OFF   + 128*HSTR*2)      // 53248 (256 f32 = 1024)
#define RGBR_OFF  (SPQ_OFF  + 1024)            // 54272
#define RGBG_OFF  (RGBR_OFF + 1024)            // 55296
#define RGBB_OFF  (RGBG_OFF + 1024)            // 56320
#define WTOT_OFF  (RGBB_OFF + 1024)            // 57344 (8 f32 warp totals + total)
#define WPART_OFF (WTOT_OFF + 64)              // 57408 (8 x 3 f32 partials)
#define B0RS_OFF  (WPART_OFF + 128)            // 57536 (128 f32)
#define B1S_OFF   (B0RS_OFF + 512)             // 58048
#define W2P_OFF   (B1S_OFF  + 512)             // 58560 (half2[3][64] = 768B)
#define B2S_OFF   (W2P_OFF  + 768)             // 59328
#define SMEM_TOTAL (B2S_OFF + 64)              // ~59.4 KB -> 2 CTAs/SM

// ---------------- PTX helpers (baseline ISA only) ----------------
__device__ __forceinline__ uint32_t smem_u32(const void* p) {
    uint32_t a;
    asm("{ .reg .u64 tmp; cvta.to.shared.u64 tmp, %1; cvt.u32.u64 %0, tmp; }" : "=r"(a) : "l"(p));
    return a;
}
#define LDSM4(r, a) \
    asm volatile("ldmatrix.sync.aligned.m8n8.x4.shared.b16 {%0,%1,%2,%3}, [%4];" \
        : "=r"((r)[0]), "=r"((r)[1]), "=r"((r)[2]), "=r"((r)[3]) : "r"(a))

// fp16-accumulator MMA: C/D = 2 regs (half2 each)
#define MMA16816H(c, a, b0_, b1_) \
    asm volatile("mma.sync.aligned.m16n8k16.row.col.f16.f16.f16.f16 " \
        "{%0,%1}, {%2,%3,%4,%5}, {%6,%7}, {%0,%1};" \
        : "+r"((c)[0]), "+r"((c)[1]) \
        : "r"((a)[0]), "r"((a)[1]), "r"((a)[2]), "r"((a)[3]), "r"(b0_), "r"(b1_))

__device__ __forceinline__ uint32_t h2pack(float lo, float hi) {
    __half2 h = __floats2half2_rn(lo, hi);     // .x = lo (low 16 bits)
    return *reinterpret_cast<uint32_t*>(&h);
}
__device__ __forceinline__ __half2 u2h2(uint32_t w) {
    return *reinterpret_cast<__half2*>(&w);
}
__device__ __forceinline__ uint32_t hmax2u(uint32_t x) {
    __half2 r = __hmax2(u2h2(x), __float2half2_rn(0.0f));
    return *reinterpret_cast<uint32_t*>(&r);
}

// ---------------- kernel 1: fused transpose/pack + per-ray bias ----------
__global__ __launch_bounds__(256) void k_prep(const float* __restrict__ dens,
                                              const float* __restrict__ k0,
                                              const float* __restrict__ vdirs,
                                              const float* __restrict__ w0g,
                                              const float* __restrict__ b0g) {
    const int t = threadIdx.x;
    const int b = blockIdx.x;

    // ---- per-ray bias (blocks 0..NRAYS-1, threads 0..127, warp-autonomous) --
    if (b < NRAYS && t < 128) {
        const int lane = t & 31;
        float vx = __ldg(vdirs + b * 3 + 0);
        float vy = __ldg(vdirs + b * 3 + 1);
        float vz = __ldg(vdirs + b * 3 + 2);
        float inv = rsqrtf(vx * vx + vy * vy + vz * vz);
        vx *= inv; vy *= inv; vz *= inv;
        float ev = 0.0f;
        if (lane < 3) {
            ev = (lane == 0) ? vx : (lane == 1) ? vy : vz;
        } else if (lane < 15) {
            int i = lane - 3, d = i >> 2, f = i & 3;
            float v = (d == 0) ? vx : (d == 1) ? vy : vz;
            ev = sinf(v * (float)(1 << f));
        } else if (lane < 27) {
            int i = lane - 15, d = i >> 2, f = i & 3;
            float v = (d == 0) ? vx : (d == 1) ? vy : vz;
            ev = cosf(v * (float)(1 << f));
        }
        float s = __ldg(b0g + t);
#pragma unroll
        for (int e = 0; e < 27; e++) {
            float embv = __shfl_sync(0xffffffffu, ev, e);
            s += embv * __ldg(w0g + (12 + e) * 128 + t);
        }
        g_b0r[(size_t)b * 128 + t] = s;
    }

    // ---- transpose + fp16-pack: 2 consecutive voxels per thread ----
    const int v0 = b * 512 + t * 2;
    float2 ch[13];
#pragma unroll
    for (int c = 0; c < 12; c++)
        ch[c] = __ldg(reinterpret_cast<const float2*>(k0 + (size_t)c * V + v0));
    ch[12] = __ldg(reinterpret_cast<const float2*>(dens + v0));

    uint32_t h0[6], h1[6];
#pragma unroll
    for (int j = 0; j < 6; j++) {
        h0[j] = h2pack(ch[2 * j].x, ch[2 * j + 1].x);
        h1[j] = h2pack(ch[2 * j].y, ch[2 * j + 1].y);
    }
    uint4* outp = g_pack + (size_t)v0 * 2;
    outp[0] = make_uint4(h0[0], h0[1], h0[2], h0[3]);
    outp[1] = make_uint4(h0[4], h0[5], __float_as_uint(ch[12].x), 0u);
    outp[2] = make_uint4(h1[0], h1[1], h1[2], h1[3]);
    outp[3] = make_uint4(h1[4], h1[5], __float_as_uint(ch[12].y), 0u);
}

// ---------------- kernel 2: persistent ray-fused featurize + MLP + composite --
// M=32 per warp; W0 and W1 B-fragments each feed 4 MMAs.
__global__ __launch_bounds__(256, 2)
void k_mlp(const float* __restrict__ pts,
           const float* __restrict__ w0g,
           const float* __restrict__ w1g, const float* __restrict__ b1g,
           const float* __restrict__ w2g, const float* __restrict__ b2g,
           float* __restrict__ out) {
    extern __shared__ char sm[];
    const uint32_t sb = smem_u32(sm);
    const int t = threadIdx.x;
    const int lane = t & 31;
    const int warp = t >> 5;

    float* spq  = reinterpret_cast<float*>(sm + SPQ_OFF);
    float* s_r  = reinterpret_cast<float*>(sm + RGBR_OFF);
    float* s_g  = reinterpret_cast<float*>(sm + RGBG_OFF);
    float* s_b  = reinterpret_cast<float*>(sm + RGBB_OFF);
    float* wtot = reinterpret_cast<float*>(sm + WTOT_OFF);
    float* wpart= reinterpret_cast<float*>(sm + WPART_OFF);
    float* b0rs = reinterpret_cast<float*>(sm + B0RS_OFF);
    float* b1s  = reinterpret_cast<float*>(sm + B1S_OFF);
    uint32_t* w2p = reinterpret_cast<uint32_t*>(sm + W2P_OFF);   // [3][64]
    float* b2s  = reinterpret_cast<float*>(sm + B2S_OFF);

    // ---- zero feat + w0 regions (K pads stay zero) ----
    for (int i = t; i < W1_OFF / 4; i += 256)
        reinterpret_cast<uint32_t*>(sm)[i] = 0;
    __syncthreads();

    // ---- stage weights (once per block) ----
    for (int i = t; i < 12 * 128; i += 256) {
        int k = i >> 7, n = i & 127;
        reinterpret_cast<__half*>(sm + W0_OFF)[n * FSTR + k] = __float2half_rn(w0g[i]);
    }
    for (int i = t; i < 128 * 128; i += 256) {
        int k = i >> 7, n = i & 127;
        reinterpret_cast<__half*>(sm + W1_OFF)[n * HSTR + k] = __float2half_rn(w1g[i]);
    }
    if (t < 128) b1s[t] = b1g[t];
    if (t < 192) {
        int c = t / 64, i = t % 64;
        w2p[c * 64 + i] = h2pack(w2g[(2 * i) * 3 + c], w2g[(2 * i + 1) * 3 + c]);
    }
    if (t < 3) b2s[t] = b2g[t];
    __syncthreads();

    // ---- ldmatrix lane addressing ----
    const int a_row = (((lane >> 3) & 1) << 3) + (lane & 7);
    const int a_k8  = (lane >> 4) << 3;
    const int b_row = ((lane >> 4) << 3) + (lane & 7);
    const int b_k8  = ((lane >> 3) & 1) << 3;

    const int m0 = warp << 5;          // 32 rows per warp
    const int lane4 = lane & 3;
    const int laneq = lane >> 2;

    for (int ray = blockIdx.x; ray < NRAYS; ray += GRID_MLP) {
        const int gs = ray * 256 + t;

        // ===== featurize: all 16 corner loads issued up-front (MLP=16) =====
        {
            const float* pp = pts + (size_t)gs * 3;
            float f[3]; int i0[3];
#pragma unroll
            for (int d = 0; d < 3; d++) {
                float u = (pp[d] + 1.0f) * (0.5f * (G - 1));
                u = fminf(fmaxf(u, 0.0f), (float)(G - 1));
                int ii = (int)floorf(u);
                ii = min(ii, G - 2);
                f[d] = u - (float)ii;
                i0[d] = ii;
            }
            float wx[2] = {1.0f - f[0], f[0]};
            float wy[2] = {1.0f - f[1], f[1]};
            float wz[2] = {1.0f - f[2], f[2]};

            const int base = (i0[0] * G + i0[1]) * G + i0[2];
            uint4 L[16];
#pragma unroll
            for (int cidx = 0; cidx < 8; cidx++) {
                int vox = base + (cidx >> 2) * (G * G) + ((cidx >> 1) & 1) * G + (cidx & 1);
                const uint4* cp = g_pack + (size_t)vox * 2;
                L[2 * cidx]     = cp[0];
                L[2 * cidx + 1] = cp[1];
            }

            __half2 acc2[6];
#pragma unroll
            for (int j = 0; j < 6; j++) acc2[j] = __float2half2_rn(0.0f);
            float dacc = 0.0f;
#pragma unroll
            for (int cidx = 0; cidx < 8; cidx++) {
                float wgt = wx[cidx >> 2] * wy[(cidx >> 1) & 1] * wz[cidx & 1];
                __half2 wh = __float2half2_rn(wgt);
                uint4 A = L[2 * cidx], B = L[2 * cidx + 1];
                acc2[0] = __hfma2(wh, u2h2(A.x), acc2[0]);
                acc2[1] = __hfma2(wh, u2h2(A.y), acc2[1]);
                acc2[2] = __hfma2(wh, u2h2(A.z), acc2[2]);
                acc2[3] = __hfma2(wh, u2h2(A.w), acc2[3]);
                acc2[4] = __hfma2(wh, u2h2(B.x), acc2[4]);
                acc2[5] = __hfma2(wh, u2h2(B.y), acc2[5]);
                dacc += wgt * __uint_as_float(B.z);
            }
            uint32_t* frow = reinterpret_cast<uint32_t*>(sm + FEAT_OFF + (size_t)t * FSTR * 2);
#pragma unroll
            for (int j = 0; j < 6; j++)
                frow[j] = *reinterpret_cast<uint32_t*>(&acc2[j]);
            float dd = dacc + ACT_SHIFT;
            float sp = (dd > 15.0f) ? dd : log1pf(expf(dd));
            spq[t] = 0.5f * sp;                   // q = INTERVAL * softplus
            if (t < 128) b0rs[t] = g_b0r[(size_t)ray * 128 + t];
        }
        __syncthreads();

        // ===== GEMM1 (fp16 acc, K=16): both subtiles share W0 B-fragments ====
        uint32_t a2[2][8][4];
        {
            uint32_t c[2][16][2];
#pragma unroll
            for (int j = 0; j < 16; j++) {
                float2 bb = *reinterpret_cast<const float2*>(b0rs + 8 * j + 2 * lane4);
                uint32_t bb2 = h2pack(bb.x, bb.y);
                c[0][j][0] = bb2; c[0][j][1] = bb2;
                c[1][j][0] = bb2; c[1][j][1] = bb2;
            }
            uint32_t ah[2][4];
            LDSM4(ah[0], sb + FEAT_OFF + ((m0 + a_row) * FSTR + a_k8) * 2);
            LDSM4(ah[1], sb + FEAT_OFF + ((m0 + 16 + a_row) * FSTR + a_k8) * 2);
#pragma unroll
            for (int g = 0; g < 8; g++) {
                uint32_t bh[4];
                LDSM4(bh, sb + W0_OFF + ((16 * g + b_row) * FSTR + b_k8) * 2);
                MMA16816H(c[0][2 * g],     ah[0], bh[0], bh[1]);
                MMA16816H(c[0][2 * g + 1], ah[0], bh[2], bh[3]);
                MMA16816H(c[1][2 * g],     ah[1], bh[0], bh[1]);
                MMA16816H(c[1][2 * g + 1], ah[1], bh[2], bh[3]);
            }
            // relu in place -> A fragments for GEMM2
#pragma unroll
            for (int sub = 0; sub < 2; sub++)
#pragma unroll
                for (int tk = 0; tk < 8; tk++) {
                    a2[sub][tk][0] = hmax2u(c[sub][2 * tk][0]);
                    a2[sub][tk][1] = hmax2u(c[sub][2 * tk][1]);
                    a2[sub][tk][2] = hmax2u(c[sub][2 * tk + 1][0]);
                    a2[sub][tk][3] = hmax2u(c[sub][2 * tk + 1][1]);
                }
        }

        // ===== GEMM2 (fp16 acc): each W1 LDSM feeds 4 MMAs =====
        uint32_t d[2][16][2];
#pragma unroll
        for (int j = 0; j < 16; j++) {
            int col0 = 8 * j + 2 * lane4;
            uint32_t bb2 = h2pack(b1s[col0], b1s[col0 + 1]);
            d[0][j][0] = bb2; d[0][j][1] = bb2;
            d[1][j][0] = bb2; d[1][j][1] = bb2;
        }
#pragma unroll
        for (int tk = 0; tk < 8; tk++) {
#pragma unroll
            for (int g = 0; g < 8; g++) {
                uint32_t wh[4];
                LDSM4(wh, sb + W1_OFF + ((16 * g + b_row) * HSTR + tk * 16 + b_k8) * 2);
                MMA16816H(d[0][2 * g],     a2[0][tk], wh[0], wh[1]);
                MMA16816H(d[0][2 * g + 1], a2[0][tk], wh[2], wh[3]);
                MMA16816H(d[1][2 * g],     a2[1][tk], wh[0], wh[1]);
                MMA16816H(d[1][2 * g + 1], a2[1][tk], wh[2], wh[3]);
            }
        }

        // ===== epilogue2 for both subtiles: rgb = sigmoid(relu(d) @ w2 + b2) ==
#pragma unroll
        for (int sub = 0; sub < 2; sub++) {
            __half2 qA0 = __float2half2_rn(0.f), qA1 = qA0, qA2 = qA0;
            __half2 qB0 = qA0, qB1 = qA0, qB2 = qA0;
#pragma unroll
            for (int j = 0; j < 16; j++) {
                int idx = 4 * j + lane4;
                __half2 hA = u2h2(hmax2u(d[sub][j][0]));
                __half2 hB = u2h2(hmax2u(d[sub][j][1]));
                __half2 w0h = u2h2(w2p[idx]);
                __half2 w1h = u2h2(w2p[64 + idx]);
                __half2 w2h = u2h2(w2p[128 + idx]);
                qA0 = __hfma2(hA, w0h, qA0);
                qA1 = __hfma2(hA, w1h, qA1);
                qA2 = __hfma2(hA, w2h, qA2);
                qB0 = __hfma2(hB, w0h, qB0);
                qB1 = __hfma2(hB, w1h, qB1);
                qB2 = __hfma2(hB, w2h, qB2);
            }
            float p00 = __low2float(qA0) + __high2float(qA0);
            float p01 = __low2float(qA1) + __high2float(qA1);
            float p02 = __low2float(qA2) + __high2float(qA2);
            float p10 = __low2float(qB0) + __high2float(qB0);
            float p11 = __low2float(qB1) + __high2float(qB1);
            float p12 = __low2float(qB2) + __high2float(qB2);
#pragma unroll
            for (int sh = 1; sh <= 2; sh <<= 1) {
                p00 += __shfl_xor_sync(0xffffffffu, p00, sh);
                p01 += __shfl_xor_sync(0xffffffffu, p01, sh);
                p02 += __shfl_xor_sync(0xffffffffu, p02, sh);
                p10 += __shfl_xor_sync(0xffffffffu, p10, sh);
                p11 += __shfl_xor_sync(0xffffffffu, p11, sh);
                p12 += __shfl_xor_sync(0xffffffffu, p12, sh);
            }
            if (lane4 == 0) {
                int r0 = m0 + 16 * sub + laneq;
                int r1 = r0 + 8;
                s_r[r0] = 1.0f / (1.0f + expf(-(p00 + b2s[0])));
                s_g[r0] = 1.0f / (1.0f + expf(-(p01 + b2s[1])));
                s_b[r0] = 1.0f / (1.0f + expf(-(p02 + b2s[2])));
                s_r[r1] = 1.0f / (1.0f + expf(-(p10 + b2s[0])));
                s_g[r1] = 1.0f / (1.0f + expf(-(p11 + b2s[1])));
                s_b[r1] = 1.0f / (1.0f + expf(-(p12 + b2s[2])));
            }
        }
        __syncthreads();

        // ===== composite (in-block): warp-shuffle scan of q, weight, reduce ====
        {
            float q = spq[t];
            float v = q;
#pragma unroll
            for (int off = 1; off < 32; off <<= 1) {
                float u = __shfl_up_sync(0xffffffffu, v, off);
                if (lane >= off) v += u;
            }
            if (lane == 31) wtot[warp] = v;
            __syncthreads();
            if (t < 8) {
                float w = wtot[t];
#pragma unroll
                for (int off = 1; off < 8; off <<= 1) {
                    float u = __shfl_up_sync(0xffu, w, off);
                    if (t >= off) w += u;
                }
                wtot[t] = w;               // inclusive warp-total scan
                if (t == 7) wtot[8] = w;   // grand total
            }
            __syncthreads();
            float incl = v + ((warp > 0) ? wtot[warp - 1] : 0.0f);
            float T_excl = expf(-(incl - q));
            float alpha = 1.0f - expf(-q);
            float wgt = alpha * T_excl;

            float rr = wgt * s_r[t];
            float gg = wgt * s_g[t];
            float bb = wgt * s_b[t];
#pragma unroll
            for (int sh = 16; sh > 0; sh >>= 1) {
                rr += __shfl_xor_sync(0xffffffffu, rr, sh);
                gg += __shfl_xor_sync(0xffffffffu, gg, sh);
                bb += __shfl_xor_sync(0xffffffffu, bb, sh);
            }
            if (lane == 0) {
                wpart[warp * 3 + 0] = rr;
                wpart[warp * 3 + 1] = gg;
                wpart[warp * 3 + 2] = bb;
            }
            __syncthreads();
            if (t == 0) {
                float ainv = expf(-wtot[8]);
                float o0 = ainv, o1 = ainv, o2 = ainv;
#pragma unroll
                for (int w8 = 0; w8 < 8; w8++) {
                    o0 += wpart[w8 * 3 + 0];
                    o1 += wpart[w8 * 3 + 1];
                    o2 += wpart[w8 * 3 + 2];
                }
                out[ray * 3 + 0] = o0;
                out[ray * 3 + 1] = o1;
                out[ray * 3 + 2] = o2;
            }
        }
        __syncthreads();
    }
}

// ---------------- launch ----------------
extern "C" void kernel_launch(void* const* d_in, const int* in_sizes, int n_in,
                              void* d_out, int out_size) {
    const float* pts      = (const float*)d_in[0];
    const float* viewdirs = (const float*)d_in[1];
    const float* dens     = (const float*)d_in[2];
    const float* k0       = (const float*)d_in[3];
    const float* w0g      = (const float*)d_in[4];
    const float* b0g      = (const float*)d_in[5];
    const float* w1g      = (const float*)d_in[6];
    const float* b1g      = (const float*)d_in[7];
    const float* w2g      = (const float*)d_in[8];
    const float* b2g      = (const float*)d_in[9];
    float* out = (float*)d_out;

    cudaFuncSetAttribute(k_mlp, cudaFuncAttributeMaxDynamicSharedMemorySize, SMEM_TOTAL);

    k_prep<<<V / 512, 256>>>(dens, k0, viewdirs, w0g, b0g);
    k_mlp<<<GRID_MLP, 256, SMEM_TOTAL>>>(pts, w0g, w1g, b1g, w2g, b2g, out);
}

// round 14
// speedup vs baseline: 1.1700x; 1.1700x over previous
#include <cuda_runtime.h>
#include <cuda_fp16.h>
#include <cstdint>
#include <math.h>

// ---------------- problem constants ----------------
#define G        160
#define V        (G*G*G)          // 4,096,000 voxels
#define NRAYS    4096
#define S        256
#define NS       (NRAYS*S)        // 1,048,576 samples
#define ACT_SHIFT (-4.5951198501345898f)   // log(0.01/0.99)

#define FSTR     24               // fp16 elems/row, feat + w0 tiles (K=16 incl pad)
#define HSTR     136              // fp16 elems/row, w1 tiles (K=128 + pad)
#define GRID_MLP 304

// ---------------- scratch ----------------
// packed voxel (16B): bytes 0-11 = ch0..11 int8 biased(+128), scaled by s;
//                     bytes 12-13 = s (fp16, = max|ch|/127); bytes 14-15 = density fp16
__device__ uint4 g_pack[(size_t)V];
__device__ float g_b0r[(size_t)NRAYS * 128];// per-ray fused bias: b0 + emb@w0[12:39]

// ---------------- smem layout (byte offsets) ----------------
#define FEAT_OFF  0                            // 256 x FSTR fp16 = 12288
#define W0_OFF    (FEAT_OFF + 256*FSTR*2)      // 12288 (+6144)
#define W1_OFF    (W0_OFF   + 128*FSTR*2)      // 18432 (+34816)
#define SPQ_OFF   (W1_OFF   + 128*HSTR*2)      // 53248 (256 f32 = 1024)
#define RGBR_OFF  (SPQ_OFF  + 1024)            // 54272
#define RGBG_OFF  (RGBR_OFF + 1024)            // 55296
#define RGBB_OFF  (RGBG_OFF + 1024)            // 56320
#define WTOT_OFF  (RGBB_OFF + 1024)            // 57344 (8 f32 warp totals + total)
#define WPART_OFF (WTOT_OFF + 64)              // 57408 (8 x 3 f32 partials)
#define B0RS_OFF  (WPART_OFF + 128)            // 57536 (128 f32)
#define B1S_OFF   (B0RS_OFF + 512)             // 58048
#define W2P_OFF   (B1S_OFF  + 512)             // 58560 (half2[3][64] = 768B)
#define B2S_OFF   (W2P_OFF  + 768)             // 59328
#define SMEM_TOTAL (B2S_OFF + 64)              // ~59.4 KB -> 2 CTAs/SM

// ---------------- PTX helpers (baseline ISA only) ----------------
__device__ __forceinline__ uint32_t smem_u32(const void* p) {
    uint32_t a;
    asm("{ .reg .u64 tmp; cvta.to.shared.u64 tmp, %1; cvt.u32.u64 %0, tmp; }" : "=r"(a) : "l"(p));
    return a;
}
#define LDSM4(r, a) \
    asm volatile("ldmatrix.sync.aligned.m8n8.x4.shared.b16 {%0,%1,%2,%3}, [%4];" \
        : "=r"((r)[0]), "=r"((r)[1]), "=r"((r)[2]), "=r"((r)[3]) : "r"(a))

// fp16-accumulator MMA: C/D = 2 regs (half2 each)
#define MMA16816H(c, a, b0_, b1_) \
    asm volatile("mma.sync.aligned.m16n8k16.row.col.f16.f16.f16.f16 " \
        "{%0,%1}, {%2,%3,%4,%5}, {%6,%7}, {%0,%1};" \
        : "+r"((c)[0]), "+r"((c)[1]) \
        : "r"((a)[0]), "r"((a)[1]), "r"((a)[2]), "r"((a)[3]), "r"(b0_), "r"(b1_))

__device__ __forceinline__ uint32_t h2pack(float lo, float hi) {
    __half2 h = __floats2half2_rn(lo, hi);     // .x = lo (low 16 bits)
    return *reinterpret_cast<uint32_t*>(&h);
}
__device__ __forceinline__ __half2 u2h2(uint32_t w) {
    return *reinterpret_cast<__half2*>(&w);
}
__device__ __forceinline__ uint32_t hmax2u(uint32_t x) {
    __half2 r = __hmax2(u2h2(x), __float2half2_rn(0.0f));
    return *reinterpret_cast<uint32_t*>(&r);
}

// ---------------- kernel 1: fused quantize/pack + per-ray bias ----------
__global__ __launch_bounds__(256) void k_prep(const float* __restrict__ dens,
                                              const float* __restrict__ k0,
                                              const float* __restrict__ vdirs,
                                              const float* __restrict__ w0g,
                                              const float* __restrict__ b0g) {
    const int t = threadIdx.x;
    const int b = blockIdx.x;

    // ---- per-ray bias (blocks 0..NRAYS-1, threads 0..127, warp-autonomous) --
    if (b < NRAYS && t < 128) {
        const int lane = t & 31;
        float vx = __ldg(vdirs + b * 3 + 0);
        float vy = __ldg(vdirs + b * 3 + 1);
        float vz = __ldg(vdirs + b * 3 + 2);
        float inv = rsqrtf(vx * vx + vy * vy + vz * vz);
        vx *= inv; vy *= inv; vz *= inv;
        float ev = 0.0f;
        if (lane < 3) {
            ev = (lane == 0) ? vx : (lane == 1) ? vy : vz;
        } else if (lane < 15) {
            int i = lane - 3, d = i >> 2, f = i & 3;
            float v = (d == 0) ? vx : (d == 1) ? vy : vz;
            ev = sinf(v * (float)(1 << f));
        } else if (lane < 27) {
            int i = lane - 15, d = i >> 2, f = i & 3;
            float v = (d == 0) ? vx : (d == 1) ? vy : vz;
            ev = cosf(v * (float)(1 << f));
        }
        float s = __ldg(b0g + t);
#pragma unroll
        for (int e = 0; e < 27; e++) {
            float embv = __shfl_sync(0xffffffffu, ev, e);
            s += embv * __ldg(w0g + (12 + e) * 128 + t);
        }
        g_b0r[(size_t)b * 128 + t] = s;
    }

    // ---- quantize + pack: 2 consecutive voxels per thread ----
    const int v0 = b * 512 + t * 2;
    float2 ch[13];
#pragma unroll
    for (int c = 0; c < 12; c++)
        ch[c] = __ldg(reinterpret_cast<const float2*>(k0 + (size_t)c * V + v0));
    ch[12] = __ldg(reinterpret_cast<const float2*>(dens + v0));

#pragma unroll
    for (int sv = 0; sv < 2; sv++) {
        float vals[12];
#pragma unroll
        for (int c = 0; c < 12; c++) vals[c] = sv ? ch[c].y : ch[c].x;
        float dv = sv ? ch[12].y : ch[12].x;

        float mx = 1e-12f;
#pragma unroll
        for (int c = 0; c < 12; c++) mx = fmaxf(mx, fabsf(vals[c]));
        float scale = mx * (1.0f / 127.0f);
        float qinv  = 127.0f / mx;
        uint32_t w[3] = {0u, 0u, 0u};
#pragma unroll
        for (int c = 0; c < 12; c++) {
            int q = __float2int_rn(vals[c] * qinv) + 128;   // [1,255]
            w[c >> 2] |= (uint32_t)q << ((c & 3) * 8);
        }
        uint32_t sw = (uint32_t)__half_as_ushort(__float2half_rn(scale))
                    | ((uint32_t)__half_as_ushort(__float2half_rn(dv)) << 16);
        g_pack[v0 + sv] = make_uint4(w[0], w[1], w[2], sw);
    }
}

// ---------------- kernel 2: persistent ray-fused featurize + MLP + composite --
// M=32 per warp; W0 and W1 B-fragments each feed 4 MMAs.
__global__ __launch_bounds__(256, 2)
void k_mlp(const float* __restrict__ pts,
           const float* __restrict__ w0g,
           const float* __restrict__ w1g, const float* __restrict__ b1g,
           const float* __restrict__ w2g, const float* __restrict__ b2g,
           float* __restrict__ out) {
    extern __shared__ char sm[];
    const uint32_t sb = smem_u32(sm);
    const int t = threadIdx.x;
    const int lane = t & 31;
    const int warp = t >> 5;

    float* spq  = reinterpret_cast<float*>(sm + SPQ_OFF);
    float* s_r  = reinterpret_cast<float*>(sm + RGBR_OFF);
    float* s_g  = reinterpret_cast<float*>(sm + RGBG_OFF);
    float* s_b  = reinterpret_cast<float*>(sm + RGBB_OFF);
    float* wtot = reinterpret_cast<float*>(sm + WTOT_OFF);
    float* wpart= reinterpret_cast<float*>(sm + WPART_OFF);
    float* b0rs = reinterpret_cast<float*>(sm + B0RS_OFF);
    float* b1s  = reinterpret_cast<float*>(sm + B1S_OFF);
    uint32_t* w2p = reinterpret_cast<uint32_t*>(sm + W2P_OFF);   // [3][64]
    float* b2s  = reinterpret_cast<float*>(sm + B2S_OFF);

    // ---- zero feat + w0 regions (K pads stay zero) ----
    for (int i = t; i < W1_OFF / 4; i += 256)
        reinterpret_cast<uint32_t*>(sm)[i] = 0;
    __syncthreads();

    // ---- stage weights (once per block) ----
    for (int i = t; i < 12 * 128; i += 256) {
        int k = i >> 7, n = i & 127;
        reinterpret_cast<__half*>(sm + W0_OFF)[n * FSTR + k] = __float2half_rn(w0g[i]);
    }
    for (int i = t; i < 128 * 128; i += 256) {
        int k = i >> 7, n = i & 127;
        reinterpret_cast<__half*>(sm + W1_OFF)[n * HSTR + k] = __float2half_rn(w1g[i]);
    }
    if (t < 128) b1s[t] = b1g[t];
    if (t < 192) {
        int c = t / 64, i = t % 64;
        w2p[c * 64 + i] = h2pack(w2g[(2 * i) * 3 + c], w2g[(2 * i + 1) * 3 + c]);
    }
    if (t < 3) b2s[t] = b2g[t];
    __syncthreads();

    // ---- ldmatrix lane addressing ----
    const int a_row = (((lane >> 3) & 1) << 3) + (lane & 7);
    const int a_k8  = (lane >> 4) << 3;
    const int b_row = ((lane >> 4) << 3) + (lane & 7);
    const int b_k8  = ((lane >> 3) & 1) << 3;

    const int m0 = warp << 5;          // 32 rows per warp
    const int lane4 = lane & 3;
    const int laneq = lane >> 2;

    const uint32_t MAGIC = 0x64646464u;      // 0x64 high-byte pattern
    const __half2  BIAS  = u2h2(0x64806480u);// 1152.0 x2

    for (int ray = blockIdx.x; ray < NRAYS; ray += GRID_MLP) {
        const int gs = ray * 256 + t;

        // ===== featurize: 8 x LDG.128 (16B/voxel), int8 dequant via prmt =====
        {
            const float* pp = pts + (size_t)gs * 3;
            float f[3]; int i0[3];
#pragma unroll
            for (int d = 0; d < 3; d++) {
                float u = (pp[d] + 1.0f) * (0.5f * (G - 1));
                u = fminf(fmaxf(u, 0.0f), (float)(G - 1));
                int ii = (int)floorf(u);
                ii = min(ii, G - 2);
                f[d] = u - (float)ii;
                i0[d] = ii;
            }
            float wx[2] = {1.0f - f[0], f[0]};
            float wy[2] = {1.0f - f[1], f[1]};
            float wz[2] = {1.0f - f[2], f[2]};

            const int base = (i0[0] * G + i0[1]) * G + i0[2];
            uint4 L[8];
#pragma unroll
            for (int cidx = 0; cidx < 8; cidx++) {
                int vox = base + (cidx >> 2) * (G * G) + ((cidx >> 1) & 1) * G + (cidx & 1);
                L[cidx] = g_pack[vox];
            }

            __half2 acc2[6];
#pragma unroll
            for (int j = 0; j < 6; j++) acc2[j] = __float2half2_rn(0.0f);
            float dacc = 0.0f;
#pragma unroll
            for (int cidx = 0; cidx < 8; cidx++) {
                float wgt = wx[cidx >> 2] * wy[(cidx >> 1) & 1] * wz[cidx & 1];
                uint4 A = L[cidx];
                float s_f = __half2float(__ushort_as_half((unsigned short)(A.w & 0xffffu)));
                float d_f = __half2float(__ushort_as_half((unsigned short)(A.w >> 16)));
                __half2 ws2 = __float2half2_rn(wgt * s_f);
                dacc += wgt * d_f;
                uint32_t p;
                p = __byte_perm(A.x, MAGIC, 0x4140);
                acc2[0] = __hfma2(ws2, __hsub2(u2h2(p), BIAS), acc2[0]);
                p = __byte_perm(A.x, MAGIC, 0x4342);
                acc2[1] = __hfma2(ws2, __hsub2(u2h2(p), BIAS), acc2[1]);
                p = __byte_perm(A.y, MAGIC, 0x4140);
                acc2[2] = __hfma2(ws2, __hsub2(u2h2(p), BIAS), acc2[2]);
                p = __byte_perm(A.y, MAGIC, 0x4342);
                acc2[3] = __hfma2(ws2, __hsub2(u2h2(p), BIAS), acc2[3]);
                p = __byte_perm(A.z, MAGIC, 0x4140);
                acc2[4] = __hfma2(ws2, __hsub2(u2h2(p), BIAS), acc2[4]);
                p = __byte_perm(A.z, MAGIC, 0x4342);
                acc2[5] = __hfma2(ws2, __hsub2(u2h2(p), BIAS), acc2[5]);
            }
            uint32_t* frow = reinterpret_cast<uint32_t*>(sm + FEAT_OFF + (size_t)t * FSTR * 2);
#pragma unroll
            for (int j = 0; j < 6; j++)
                frow[j] = *reinterpret_cast<uint32_t*>(&acc2[j]);
            float dd = dacc + ACT_SHIFT;
            float sp = (dd > 15.0f) ? dd : log1pf(expf(dd));
            spq[t] = 0.5f * sp;                   // q = INTERVAL * softplus
            if (t < 128) b0rs[t] = g_b0r[(size_t)ray * 128 + t];
        }
        __syncthreads();

        // ===== GEMM1 (fp16 acc, K=16): both subtiles share W0 B-fragments ====
        uint32_t a2[2][8][4];
        {
            uint32_t c[2][16][2];
#pragma unroll
            for (int j = 0; j < 16; j++) {
                float2 bb = *reinterpret_cast<const float2*>(b0rs + 8 * j + 2 * lane4);
                uint32_t bb2 = h2pack(bb.x, bb.y);
                c[0][j][0] = bb2; c[0][j][1] = bb2;
                c[1][j][0] = bb2; c[1][j][1] = bb2;
            }
            uint32_t ah[2][4];
            LDSM4(ah[0], sb + FEAT_OFF + ((m0 + a_row) * FSTR + a_k8) * 2);
            LDSM4(ah[1], sb + FEAT_OFF + ((m0 + 16 + a_row) * FSTR + a_k8) * 2);
#pragma unroll
            for (int g = 0; g < 8; g++) {
                uint32_t bh[4];
                LDSM4(bh, sb + W0_OFF + ((16 * g + b_row) * FSTR + b_k8) * 2);
                MMA16816H(c[0][2 * g],     ah[0], bh[0], bh[1]);
                MMA16816H(c[0][2 * g + 1], ah[0], bh[2], bh[3]);
                MMA16816H(c[1][2 * g],     ah[1], bh[0], bh[1]);
                MMA16816H(c[1][2 * g + 1], ah[1], bh[2], bh[3]);
            }
            // relu in place -> A fragments for GEMM2
#pragma unroll
            for (int sub = 0; sub < 2; sub++)
#pragma unroll
                for (int tk = 0; tk < 8; tk++) {
                    a2[sub][tk][0] = hmax2u(c[sub][2 * tk][0]);
                    a2[sub][tk][1] = hmax2u(c[sub][2 * tk][1]);
                    a2[sub][tk][2] = hmax2u(c[sub][2 * tk + 1][0]);
                    a2[sub][tk][3] = hmax2u(c[sub][2 * tk + 1][1]);
                }
        }

        // ===== GEMM2 (fp16 acc): each W1 LDSM feeds 4 MMAs =====
        uint32_t d[2][16][2];
#pragma unroll
        for (int j = 0; j < 16; j++) {
            int col0 = 8 * j + 2 * lane4;
            uint32_t bb2 = h2pack(b1s[col0], b1s[col0 + 1]);
            d[0][j][0] = bb2; d[0][j][1] = bb2;
            d[1][j][0] = bb2; d[1][j][1] = bb2;
        }
#pragma unroll
        for (int tk = 0; tk < 8; tk++) {
#pragma unroll
            for (int g = 0; g < 8; g++) {
                uint32_t wh[4];
                LDSM4(wh, sb + W1_OFF + ((16 * g + b_row) * HSTR + tk * 16 + b_k8) * 2);
                MMA16816H(d[0][2 * g],     a2[0][tk], wh[0], wh[1]);
                MMA16816H(d[0][2 * g + 1], a2[0][tk], wh[2], wh[3]);
                MMA16816H(d[1][2 * g],     a2[1][tk], wh[0], wh[1]);
                MMA16816H(d[1][2 * g + 1], a2[1][tk], wh[2], wh[3]);
            }
        }

        // ===== epilogue2 for both subtiles: rgb = sigmoid(relu(d) @ w2 + b2) ==
#pragma unroll
        for (int sub = 0; sub < 2; sub++) {
            __half2 qA0 = __float2half2_rn(0.f), qA1 = qA0, qA2 = qA0;
            __half2 qB0 = qA0, qB1 = qA0, qB2 = qA0;
#pragma unroll
            for (int j = 0; j < 16; j++) {
                int idx = 4 * j + lane4;
                __half2 hA = u2h2(hmax2u(d[sub][j][0]));
                __half2 hB = u2h2(hmax2u(d[sub][j][1]));
                __half2 w0h = u2h2(w2p[idx]);
                __half2 w1h = u2h2(w2p[64 + idx]);
                __half2 w2h = u2h2(w2p[128 + idx]);
                qA0 = __hfma2(hA, w0h, qA0);
                qA1 = __hfma2(hA, w1h, qA1);
                qA2 = __hfma2(hA, w2h, qA2);
                qB0 = __hfma2(hB, w0h, qB0);
                qB1 = __hfma2(hB, w1h, qB1);
                qB2 = __hfma2(hB, w2h, qB2);
            }
            float p00 = __low2float(qA0) + __high2float(qA0);
            float p01 = __low2float(qA1) + __high2float(qA1);
            float p02 = __low2float(qA2) + __high2float(qA2);
            float p10 = __low2float(qB0) + __high2float(qB0);
            float p11 = __low2float(qB1) + __high2float(qB1);
            float p12 = __low2float(qB2) + __high2float(qB2);
#pragma unroll
            for (int sh = 1; sh <= 2; sh <<= 1) {
                p00 += __shfl_xor_sync(0xffffffffu, p00, sh);
                p01 += __shfl_xor_sync(0xffffffffu, p01, sh);
                p02 += __shfl_xor_sync(0xffffffffu, p02, sh);
                p10 += __shfl_xor_sync(0xffffffffu, p10, sh);
                p11 += __shfl_xor_sync(0xffffffffu, p11, sh);
                p12 += __shfl_xor_sync(0xffffffffu, p12, sh);
            }
            if (lane4 == 0) {
                int r0 = m0 + 16 * sub + laneq;
                int r1 = r0 + 8;
                s_r[r0] = 1.0f / (1.0f + expf(-(p00 + b2s[0])));
                s_g[r0] = 1.0f / (1.0f + expf(-(p01 + b2s[1])));
                s_b[r0] = 1.0f / (1.0f + expf(-(p02 + b2s[2])));
                s_r[r1] = 1.0f / (1.0f + expf(-(p10 + b2s[0])));
                s_g[r1] = 1.0f / (1.0f + expf(-(p11 + b2s[1])));
                s_b[r1] = 1.0f / (1.0f + expf(-(p12 + b2s[2])));
            }
        }
        __syncthreads();

        // ===== composite (in-block): warp-shuffle scan of q, weight, reduce ====
        {
            float q = spq[t];
            float v = q;
#pragma unroll
            for (int off = 1; off < 32; off <<= 1) {
                float u = __shfl_up_sync(0xffffffffu, v, off);
                if (lane >= off) v += u;
            }
            if (lane == 31) wtot[warp] = v;
            __syncthreads();
            if (t < 8) {
                float w = wtot[t];
#pragma unroll
                for (int off = 1; off < 8; off <<= 1) {
                    float u = __shfl_up_sync(0xffu, w, off);
                    if (t >= off) w += u;
                }
                wtot[t] = w;               // inclusive warp-total scan
                if (t == 7) wtot[8] = w;   // grand total
            }
            __syncthreads();
            float incl = v + ((warp > 0) ? wtot[warp - 1] : 0.0f);
            float T_excl = expf(-(incl - q));
            float alpha = 1.0f - expf(-q);
            float wgt = alpha * T_excl;

            float rr = wgt * s_r[t];
            float gg = wgt * s_g[t];
            float bb = wgt * s_b[t];
#pragma unroll
            for (int sh = 16; sh > 0; sh >>= 1) {
                rr += __shfl_xor_sync(0xffffffffu, rr, sh);
                gg += __shfl_xor_sync(0xffffffffu, gg, sh);
                bb += __shfl_xor_sync(0xffffffffu, bb, sh);
            }
            if (lane == 0) {
                wpart[warp * 3 + 0] = rr;
                wpart[warp * 3 + 1] = gg;
                wpart[warp * 3 + 2] = bb;
            }
            __syncthreads();
            if (t == 0) {
                float ainv = expf(-wtot[8]);
                float o0 = ainv, o1 = ainv, o2 = ainv;
#pragma unroll
                for (int w8 = 0; w8 < 8; w8++) {
                    o0 += wpart[w8 * 3 + 0];
                    o1 += wpart[w8 * 3 + 1];
                    o2 += wpart[w8 * 3 + 2];
                }
                out[ray * 3 + 0] = o0;
                out[ray * 3 + 1] = o1;
                out[ray * 3 + 2] = o2;
            }
        }
        __syncthreads();
    }
}

// ---------------- launch ----------------
extern "C" void kernel_launch(void* const* d_in, const int* in_sizes, int n_in,
                              void* d_out, int out_size) {
    const float* pts      = (const float*)d_in[0];
    const float* viewdirs = (const float*)d_in[1];
    const float* dens     = (const float*)d_in[2];
    const float* k0       = (const float*)d_in[3];
    const float* w0g      = (const float*)d_in[4];
    const float* b0g      = (const float*)d_in[5];
    const float* w1g      = (const float*)d_in[6];
    const float* b1g      = (const float*)d_in[7];
    const float* w2g      = (const float*)d_in[8];
    const float* b2g      = (const float*)d_in[9];
    float* out = (float*)d_out;

    cudaFuncSetAttribute(k_mlp, cudaFuncAttributeMaxDynamicSharedMemorySize, SMEM_TOTAL);

    k_prep<<<V / 512, 256>>>(dens, k0, viewdirs, w0g, b0g);
    k_mlp<<<GRID_MLP, 256, SMEM_TOTAL>>>(pts, w0g, w1g, b1g, w2g, b2g, out);
}

// round 15
// speedup vs baseline: 1.1877x; 1.0151x over previous
#include <cuda_runtime.h>
#include <cuda_fp16.h>
#include <cstdint>
#include <math.h>

// ---------------- problem constants ----------------
#define G        160
#define V        (G*G*G)          // 4,096,000 voxels
#define NRAYS    4096
#define S        256
#define NS       (NRAYS*S)        // 1,048,576 samples
#define ACT_SHIFT (-4.5951198501345898f)   // log(0.01/0.99)

#define FSTR     24               // fp16 elems/row, feat + w0 tiles (K=16 incl pad)
#define HSTR     136              // fp16 elems/row, w1 tiles (K=128 + pad)
#define GRID_MLP 304

// ---------------- scratch ----------------
// packed voxel (16B): bytes 0-11 = ch0..11 int8 biased(+128), scaled by s;
//                     bytes 12-13 = s (fp16, = max|ch|/127); bytes 14-15 = density fp16
__device__ uint4 g_pack[(size_t)V];
__device__ float g_b0r[(size_t)NRAYS * 128];// per-ray fused bias: b0 + emb@w0[12:39]

// ---------------- smem layout (byte offsets) ----------------
#define FEAT_OFF  0                            // 256 x FSTR fp16 = 12288
#define W0_OFF    (FEAT_OFF + 256*FSTR*2)      // 12288 (+6144)
#define W1_OFF    (W0_OFF   + 128*FSTR*2)      // 18432 (+34816)
#define SPQ_OFF   (W1_OFF   + 128*HSTR*2)      // 53248 (256 f32 = 1024)
#define RGBR_OFF  (SPQ_OFF  + 1024)            // 54272
#define RGBG_OFF  (RGBR_OFF + 1024)            // 55296
#define RGBB_OFF  (RGBG_OFF + 1024)            // 56320
#define WTOT_OFF  (RGBB_OFF + 1024)            // 57344 (8 f32 warp totals + total)
#define WPART_OFF (WTOT_OFF + 64)              // 57408 (8 x 3 f32 partials)
#define B0RS_OFF  (WPART_OFF + 128)            // 57536 (128 f32)
#define B1S_OFF   (B0RS_OFF + 512)             // 58048
#define W2P_OFF   (B1S_OFF  + 512)             // 58560 (half2[3][64] = 768B)
#define B2S_OFF   (W2P_OFF  + 768)             // 59328
#define SMEM_TOTAL (B2S_OFF + 64)              // ~59.4 KB -> 2 CTAs/SM

// ---------------- PTX helpers (baseline ISA only) ----------------
__device__ __forceinline__ uint32_t smem_u32(const void* p) {
    uint32_t a;
    asm("{ .reg .u64 tmp; cvta.to.shared.u64 tmp, %1; cvt.u32.u64 %0, tmp; }" : "=r"(a) : "l"(p));
    return a;
}
#define LDSM4(r, a) \
    asm volatile("ldmatrix.sync.aligned.m8n8.x4.shared.b16 {%0,%1,%2,%3}, [%4];" \
        : "=r"((r)[0]), "=r"((r)[1]), "=r"((r)[2]), "=r"((r)[3]) : "r"(a))

// fp16-accumulator MMA: C/D = 2 regs (half2 each)
#define MMA16816H(c, a, b0_, b1_) \
    asm volatile("mma.sync.aligned.m16n8k16.row.col.f16.f16.f16.f16 " \
        "{%0,%1}, {%2,%3,%4,%5}, {%6,%7}, {%0,%1};" \
        : "+r"((c)[0]), "+r"((c)[1]) \
        : "r"((a)[0]), "r"((a)[1]), "r"((a)[2]), "r"((a)[3]), "r"(b0_), "r"(b1_))

__device__ __forceinline__ uint32_t h2pack(float lo, float hi) {
    __half2 h = __floats2half2_rn(lo, hi);     // .x = lo (low 16 bits)
    return *reinterpret_cast<uint32_t*>(&h);
}
__device__ __forceinline__ __half2 u2h2(uint32_t w) {
    return *reinterpret_cast<__half2*>(&w);
}
__device__ __forceinline__ uint32_t hmax2u(uint32_t x) {
    __half2 r = __hmax2(u2h2(x), __float2half2_rn(0.0f));
    return *reinterpret_cast<uint32_t*>(&r);
}

// ---------------- kernel 1: fused quantize/pack + per-ray bias ----------
__global__ __launch_bounds__(256) void k_prep(const float* __restrict__ dens,
                                              const float* __restrict__ k0,
                                              const float* __restrict__ vdirs,
                                              const float* __restrict__ w0g,
                                              const float* __restrict__ b0g) {
    const int t = threadIdx.x;
    const int b = blockIdx.x;

    // ---- per-ray bias (blocks 0..NRAYS-1, threads 0..127, warp-autonomous) --
    if (b < NRAYS && t < 128) {
        const int lane = t & 31;
        float vx = __ldg(vdirs + b * 3 + 0);
        float vy = __ldg(vdirs + b * 3 + 1);
        float vz = __ldg(vdirs + b * 3 + 2);
        float inv = rsqrtf(vx * vx + vy * vy + vz * vz);
        vx *= inv; vy *= inv; vz *= inv;
        float ev = 0.0f;
        if (lane < 3) {
            ev = (lane == 0) ? vx : (lane == 1) ? vy : vz;
        } else if (lane < 15) {
            int i = lane - 3, d = i >> 2, f = i & 3;
            float v = (d == 0) ? vx : (d == 1) ? vy : vz;
            ev = sinf(v * (float)(1 << f));
        } else if (lane < 27) {
            int i = lane - 15, d = i >> 2, f = i & 3;
            float v = (d == 0) ? vx : (d == 1) ? vy : vz;
            ev = cosf(v * (float)(1 << f));
        }
        float s = __ldg(b0g + t);
#pragma unroll
        for (int e = 0; e < 27; e++) {
            float embv = __shfl_sync(0xffffffffu, ev, e);
            s += embv * __ldg(w0g + (12 + e) * 128 + t);
        }
        g_b0r[(size_t)b * 128 + t] = s;
    }

    // ---- quantize + pack: 2 consecutive voxels per thread ----
    const int v0 = b * 512 + t * 2;
    float2 ch[13];
#pragma unroll
    for (int c = 0; c < 12; c++)
        ch[c] = __ldg(reinterpret_cast<const float2*>(k0 + (size_t)c * V + v0));
    ch[12] = __ldg(reinterpret_cast<const float2*>(dens + v0));

#pragma unroll
    for (int sv = 0; sv < 2; sv++) {
        float vals[12];
#pragma unroll
        for (int c = 0; c < 12; c++) vals[c] = sv ? ch[c].y : ch[c].x;
        float dv = sv ? ch[12].y : ch[12].x;

        float mx = 1e-12f;
#pragma unroll
        for (int c = 0; c < 12; c++) mx = fmaxf(mx, fabsf(vals[c]));
        float scale = mx * (1.0f / 127.0f);
        float qinv  = 127.0f / mx;
        uint32_t w[3] = {0u, 0u, 0u};
#pragma unroll
        for (int c = 0; c < 12; c++) {
            int q = __float2int_rn(vals[c] * qinv) + 128;   // [1,255]
            w[c >> 2] |= (uint32_t)q << ((c & 3) * 8);
        }
        uint32_t sw = (uint32_t)__half_as_ushort(__float2half_rn(scale))
                    | ((uint32_t)__half_as_ushort(__float2half_rn(dv)) << 16);
        g_pack[v0 + sv] = make_uint4(w[0], w[1], w[2], sw);
    }
}

// ---------------- kernel 2: persistent ray-fused featurize + MLP + composite --
// M=32 per warp; W0/W1 B-fragments each feed 4 MMAs; next-ray corner loads
// software-pipelined behind the MMA/epilogue/composite phases.
__global__ __launch_bounds__(256, 2)
void k_mlp(const float* __restrict__ pts,
           const float* __restrict__ w0g,
           const float* __restrict__ w1g, const float* __restrict__ b1g,
           const float* __restrict__ w2g, const float* __restrict__ b2g,
           float* __restrict__ out) {
    extern __shared__ char sm[];
    const uint32_t sb = smem_u32(sm);
    const int t = threadIdx.x;
    const int lane = t & 31;
    const int warp = t >> 5;

    float* spq  = reinterpret_cast<float*>(sm + SPQ_OFF);
    float* s_r  = reinterpret_cast<float*>(sm + RGBR_OFF);
    float* s_g  = reinterpret_cast<float*>(sm + RGBG_OFF);
    float* s_b  = reinterpret_cast<float*>(sm + RGBB_OFF);
    float* wtot = reinterpret_cast<float*>(sm + WTOT_OFF);
    float* wpart= reinterpret_cast<float*>(sm + WPART_OFF);
    float* b0rs = reinterpret_cast<float*>(sm + B0RS_OFF);
    float* b1s  = reinterpret_cast<float*>(sm + B1S_OFF);
    uint32_t* w2p = reinterpret_cast<uint32_t*>(sm + W2P_OFF);   // [3][64]
    float* b2s  = reinterpret_cast<float*>(sm + B2S_OFF);

    // ---- zero feat + w0 regions (K pads stay zero) ----
    for (int i = t; i < W1_OFF / 4; i += 256)
        reinterpret_cast<uint32_t*>(sm)[i] = 0;
    __syncthreads();

    // ---- stage weights (once per block) ----
    for (int i = t; i < 12 * 128; i += 256) {
        int k = i >> 7, n = i & 127;
        reinterpret_cast<__half*>(sm + W0_OFF)[n * FSTR + k] = __float2half_rn(w0g[i]);
    }
    for (int i = t; i < 128 * 128; i += 256) {
        int k = i >> 7, n = i & 127;
        reinterpret_cast<__half*>(sm + W1_OFF)[n * HSTR + k] = __float2half_rn(w1g[i]);
    }
    if (t < 128) b1s[t] = b1g[t];
    if (t < 192) {
        int c = t / 64, i = t % 64;
        w2p[c * 64 + i] = h2pack(w2g[(2 * i) * 3 + c], w2g[(2 * i + 1) * 3 + c]);
    }
    if (t < 3) b2s[t] = b2g[t];
    __syncthreads();

    // ---- ldmatrix lane addressing ----
    const int a_row = (((lane >> 3) & 1) << 3) + (lane & 7);
    const int a_k8  = (lane >> 4) << 3;
    const int b_row = ((lane >> 4) << 3) + (lane & 7);
    const int b_k8  = ((lane >> 3) & 1) << 3;

    const int m0 = warp << 5;          // 32 rows per warp
    const int lane4 = lane & 3;
    const int laneq = lane >> 2;

    const uint32_t MAGIC = 0x64646464u;      // 0x64 high-byte pattern
    const __half2  BIAS  = u2h2(0x64806480u);// 1152.0 x2

    // ---- prefetch state (registers) ----
    float pf_f0, pf_f1, pf_f2;
    uint4 L[8];
    float pf_bias;

    // prologue: prefetch first ray's corners
    {
        const int gs0 = blockIdx.x * 256 + t;
        const float* pp = pts + (size_t)gs0 * 3;
        float f[3]; int i0[3];
#pragma unroll
        for (int d = 0; d < 3; d++) {
            float u = (pp[d] + 1.0f) * (0.5f * (G - 1));
            u = fminf(fmaxf(u, 0.0f), (float)(G - 1));
            int ii = (int)floorf(u);
            ii = min(ii, G - 2);
            f[d] = u - (float)ii;
            i0[d] = ii;
        }
        pf_f0 = f[0]; pf_f1 = f[1]; pf_f2 = f[2];
        const int base = (i0[0] * G + i0[1]) * G + i0[2];
#pragma unroll
        for (int cidx = 0; cidx < 8; cidx++) {
            int vox = base + (cidx >> 2) * (G * G) + ((cidx >> 1) & 1) * G + (cidx & 1);
            L[cidx] = g_pack[vox];
        }
        pf_bias = (t < 128) ? g_b0r[(size_t)blockIdx.x * 128 + t] : 0.0f;
    }

    for (int ray = blockIdx.x; ray < NRAYS; ray += GRID_MLP) {
        const int gs = ray * 256 + t;

        // ===== featurize: consume prefetched corners =====
        {
            float wx[2] = {1.0f - pf_f0, pf_f0};
            float wy[2] = {1.0f - pf_f1, pf_f1};
            float wz[2] = {1.0f - pf_f2, pf_f2};

            __half2 acc2[6];
#pragma unroll
            for (int j = 0; j < 6; j++) acc2[j] = __float2half2_rn(0.0f);
            float dacc = 0.0f;
#pragma unroll
            for (int cidx = 0; cidx < 8; cidx++) {
                float wgt = wx[cidx >> 2] * wy[(cidx >> 1) & 1] * wz[cidx & 1];
                uint4 A = L[cidx];
                float s_f = __half2float(__ushort_as_half((unsigned short)(A.w & 0xffffu)));
                float d_f = __half2float(__ushort_as_half((unsigned short)(A.w >> 16)));
                __half2 ws2 = __float2half2_rn(wgt * s_f);
                dacc += wgt * d_f;
                uint32_t p;
                p = __byte_perm(A.x, MAGIC, 0x4140);
                acc2[0] = __hfma2(ws2, __hsub2(u2h2(p), BIAS), acc2[0]);
                p = __byte_perm(A.x, MAGIC, 0x4342);
                acc2[1] = __hfma2(ws2, __hsub2(u2h2(p), BIAS), acc2[1]);
                p = __byte_perm(A.y, MAGIC, 0x4140);
                acc2[2] = __hfma2(ws2, __hsub2(u2h2(p), BIAS), acc2[2]);
                p = __byte_perm(A.y, MAGIC, 0x4342);
                acc2[3] = __hfma2(ws2, __hsub2(u2h2(p), BIAS), acc2[3]);
                p = __byte_perm(A.z, MAGIC, 0x4140);
                acc2[4] = __hfma2(ws2, __hsub2(u2h2(p), BIAS), acc2[4]);
                p = __byte_perm(A.z, MAGIC, 0x4342);
                acc2[5] = __hfma2(ws2, __hsub2(u2h2(p), BIAS), acc2[5]);
            }
            uint32_t* frow = reinterpret_cast<uint32_t*>(sm + FEAT_OFF + (size_t)t * FSTR * 2);
#pragma unroll
            for (int j = 0; j < 6; j++)
                frow[j] = *reinterpret_cast<uint32_t*>(&acc2[j]);
            float dd = dacc + ACT_SHIFT;
            float sp = (dd > 15.0f) ? dd : log1pf(expf(dd));
            spq[t] = 0.5f * sp;                   // q = INTERVAL * softplus
            if (t < 128) b0rs[t] = pf_bias;
        }
        __syncthreads();

        // ===== GEMM1 (fp16 acc, K=16): both subtiles share W0 B-fragments ====
        uint32_t a2[2][8][4];
        {
            uint32_t c[2][16][2];
#pragma unroll
            for (int j = 0; j < 16; j++) {
                float2 bb = *reinterpret_cast<const float2*>(b0rs + 8 * j + 2 * lane4);
                uint32_t bb2 = h2pack(bb.x, bb.y);
                c[0][j][0] = bb2; c[0][j][1] = bb2;
                c[1][j][0] = bb2; c[1][j][1] = bb2;
            }
            uint32_t ah[2][4];
            LDSM4(ah[0], sb + FEAT_OFF + ((m0 + a_row) * FSTR + a_k8) * 2);
            LDSM4(ah[1], sb + FEAT_OFF + ((m0 + 16 + a_row) * FSTR + a_k8) * 2);
#pragma unroll
            for (int g = 0; g < 8; g++) {
                uint32_t bh[4];
                LDSM4(bh, sb + W0_OFF + ((16 * g + b_row) * FSTR + b_k8) * 2);
                MMA16816H(c[0][2 * g],     ah[0], bh[0], bh[1]);
                MMA16816H(c[0][2 * g + 1], ah[0], bh[2], bh[3]);
                MMA16816H(c[1][2 * g],     ah[1], bh[0], bh[1]);
                MMA16816H(c[1][2 * g + 1], ah[1], bh[2], bh[3]);
            }
            // relu in place -> A fragments for GEMM2
#pragma unroll
            for (int sub = 0; sub < 2; sub++)
#pragma unroll
                for (int tk = 0; tk < 8; tk++) {
                    a2[sub][tk][0] = hmax2u(c[sub][2 * tk][0]);
                    a2[sub][tk][1] = hmax2u(c[sub][2 * tk][1]);
                    a2[sub][tk][2] = hmax2u(c[sub][2 * tk + 1][0]);
                    a2[sub][tk][3] = hmax2u(c[sub][2 * tk + 1][1]);
                }
        }

        // ===== GEMM2 (fp16 acc): each W1 LDSM feeds 4 MMAs =====
        uint32_t d[2][16][2];
#pragma unroll
        for (int j = 0; j < 16; j++) {
            int col0 = 8 * j + 2 * lane4;
            uint32_t bb2 = h2pack(b1s[col0], b1s[col0 + 1]);
            d[0][j][0] = bb2; d[0][j][1] = bb2;
            d[1][j][0] = bb2; d[1][j][1] = bb2;
        }
#pragma unroll
        for (int tk = 0; tk < 8; tk++) {
#pragma unroll
            for (int g = 0; g < 8; g++) {
                uint32_t wh[4];
                LDSM4(wh, sb + W1_OFF + ((16 * g + b_row) * HSTR + tk * 16 + b_k8) * 2);
                MMA16816H(d[0][2 * g],     a2[0][tk], wh[0], wh[1]);
                MMA16816H(d[0][2 * g + 1], a2[0][tk], wh[2], wh[3]);
                MMA16816H(d[1][2 * g],     a2[1][tk], wh[0], wh[1]);
                MMA16816H(d[1][2 * g + 1], a2[1][tk], wh[2], wh[3]);
            }
        }

        // ===== prefetch NEXT ray's corners (overlaps epilogue + composite) ====
        {
            int nray = ray + GRID_MLP;
            int pr = (nray < NRAYS) ? nray : ray;      // harmless reload on last iter
            const int gsn = pr * 256 + t;
            const float* pp = pts + (size_t)gsn * 3;
            float f[3]; int i0[3];
#pragma unroll
            for (int dd2 = 0; dd2 < 3; dd2++) {
                float u = (pp[dd2] + 1.0f) * (0.5f * (G - 1));
                u = fminf(fmaxf(u, 0.0f), (float)(G - 1));
                int ii = (int)floorf(u);
                ii = min(ii, G - 2);
                f[dd2] = u - (float)ii;
                i0[dd2] = ii;
            }
            pf_f0 = f[0]; pf_f1 = f[1]; pf_f2 = f[2];
            const int base = (i0[0] * G + i0[1]) * G + i0[2];
#pragma unroll
            for (int cidx = 0; cidx < 8; cidx++) {
                int vox = base + (cidx >> 2) * (G * G) + ((cidx >> 1) & 1) * G + (cidx & 1);
                L[cidx] = g_pack[vox];
            }
            pf_bias = (t < 128) ? g_b0r[(size_t)pr * 128 + t] : 0.0f;
        }

        // ===== epilogue2 for both subtiles: rgb = sigmoid(relu(d) @ w2 + b2) ==
#pragma unroll
        for (int sub = 0; sub < 2; sub++) {
            __half2 qA0 = __float2half2_rn(0.f), qA1 = qA0, qA2 = qA0;
            __half2 qB0 = qA0, qB1 = qA0, qB2 = qA0;
#pragma unroll
            for (int j = 0; j < 16; j++) {
                int idx = 4 * j + lane4;
                __half2 hA = u2h2(hmax2u(d[sub][j][0]));
                __half2 hB = u2h2(hmax2u(d[sub][j][1]));
                __half2 w0h = u2h2(w2p[idx]);
                __half2 w1h = u2h2(w2p[64 + idx]);
                __half2 w2h = u2h2(w2p[128 + idx]);
                qA0 = __hfma2(hA, w0h, qA0);
                qA1 = __hfma2(hA, w1h, qA1);
                qA2 = __hfma2(hA, w2h, qA2);
                qB0 = __hfma2(hB, w0h, qB0);
                qB1 = __hfma2(hB, w1h, qB1);
                qB2 = __hfma2(hB, w2h, qB2);
            }
            float p00 = __low2float(qA0) + __high2float(qA0);
            float p01 = __low2float(qA1) + __high2float(qA1);
            float p02 = __low2float(qA2) + __high2float(qA2);
            float p10 = __low2float(qB0) + __high2float(qB0);
            float p11 = __low2float(qB1) + __high2float(qB1);
            float p12 = __low2float(qB2) + __high2float(qB2);
#pragma unroll
            for (int sh = 1; sh <= 2; sh <<= 1) {
                p00 += __shfl_xor_sync(0xffffffffu, p00, sh);
                p01 += __shfl_xor_sync(0xffffffffu, p01, sh);
                p02 += __shfl_xor_sync(0xffffffffu, p02, sh);
                p10 += __shfl_xor_sync(0xffffffffu, p10, sh);
                p11 += __shfl_xor_sync(0xffffffffu, p11, sh);
                p12 += __shfl_xor_sync(0xffffffffu, p12, sh);
            }
            if (lane4 == 0) {
                int r0 = m0 + 16 * sub + laneq;
                int r1 = r0 + 8;
                s_r[r0] = 1.0f / (1.0f + expf(-(p00 + b2s[0])));
                s_g[r0] = 1.0f / (1.0f + expf(-(p01 + b2s[1])));
                s_b[r0] = 1.0f / (1.0f + expf(-(p02 + b2s[2])));
                s_r[r1] = 1.0f / (1.0f + expf(-(p10 + b2s[0])));
                s_g[r1] = 1.0f / (1.0f + expf(-(p11 + b2s[1])));
                s_b[r1] = 1.0f / (1.0f + expf(-(p12 + b2s[2])));
            }
        }
        __syncthreads();

        // ===== composite (in-block): warp-shuffle scan of q, weight, reduce ====
        {
            float q = spq[t];
            float v = q;
#pragma unroll
            for (int off = 1; off < 32; off <<= 1) {
                float u = __shfl_up_sync(0xffffffffu, v, off);
                if (lane >= off) v += u;
            }
            if (lane == 31) wtot[warp] = v;
            __syncthreads();
            if (t < 8) {
                float w = wtot[t];
#pragma unroll
                for (int off = 1; off < 8; off <<= 1) {
                    float u = __shfl_up_sync(0xffu, w, off);
                    if (t >= off) w += u;
                }
                wtot[t] = w;               // inclusive warp-total scan
                if (t == 7) wtot[8] = w;   // grand total
            }
            __syncthreads();
            float incl = v + ((warp > 0) ? wtot[warp - 1] : 0.0f);
            float T_excl = expf(-(incl - q));
            float alpha = 1.0f - expf(-q);
            float wgt = alpha * T_excl;

            float rr = wgt * s_r[t];
            float gg = wgt * s_g[t];
            float bb = wgt * s_b[t];
#pragma unroll
            for (int sh = 16; sh > 0; sh >>= 1) {
                rr += __shfl_xor_sync(0xffffffffu, rr, sh);
                gg += __shfl_xor_sync(0xffffffffu, gg, sh);
                bb += __shfl_xor_sync(0xffffffffu, bb, sh);
            }
            if (lane == 0) {
                wpart[warp * 3 + 0] = rr;
                wpart[warp * 3 + 1] = gg;
                wpart[warp * 3 + 2] = bb;
            }
            __syncthreads();
            if (t == 0) {
                float ainv = expf(-wtot[8]);
                float o0 = ainv, o1 = ainv, o2 = ainv;
#pragma unroll
                for (int w8 = 0; w8 < 8; w8++) {
                    o0 += wpart[w8 * 3 + 0];
                    o1 += wpart[w8 * 3 + 1];
                    o2 += wpart[w8 * 3 + 2];
                }
                out[ray * 3 + 0] = o0;
                out[ray * 3 + 1] = o1;
                out[ray * 3 + 2] = o2;
            }
        }
        __syncthreads();
    }
}

// ---------------- launch ----------------
extern "C" void kernel_launch(void* const* d_in, const int* in_sizes, int n_in,
                              void* d_out, int out_size) {
    const float* pts      = (const float*)d_in[0];
    const float* viewdirs = (const float*)d_in[1];
    const float* dens     = (const float*)d_in[2];
    const float* k0       = (const float*)d_in[3];
    const float* w0g      = (const float*)d_in[4];
    const float* b0g      = (const float*)d_in[5];
    const float* w1g      = (const float*)d_in[6];
    const float* b1g      = (const float*)d_in[7];
    const float* w2g      = (const float*)d_in[8];
    const float* b2g      = (const float*)d_in[9];
    float* out = (float*)d_out;

    cudaFuncSetAttribute(k_mlp, cudaFuncAttributeMaxDynamicSharedMemorySize, SMEM_TOTAL);

    k_prep<<<V / 512, 256>>>(dens, k0, viewdirs, w0g, b0g);
    k_mlp<<<GRID_MLP, 256, SMEM_TOTAL>>>(pts, w0g, w1g, b1g, w2g, b2g, out);
}